// round 9
// baseline (speedup 1.0000x reference)
#include <cuda_runtime.h>

// Fixed shapes: B=16, H=W=1536
#define H_DIM  1536
#define W_DIM  1536
#define B_DIM  16
#define HW     (H_DIM * W_DIM)      // 2359296
#define HW4    (HW / 4)             // 589824 float4 per plane
#define W4     (W_DIM / 4)          // 384 float4 per row
#define TPB    192                  // 192 threads x 8 floats = one full row

// 36-bit tile masks, bit index = (r%6)*6 + (c%6)
#define R_MASK ((1ull<<4)|(1ull<<6)|(1ull<<8)|(1ull<<16)|(1ull<<19)|(1ull<<27)|(1ull<<29)|(1ull<<31))
#define B_MASK ((1ull<<1)|(1ull<<9)|(1ull<<11)|(1ull<<13)|(1ull<<22)|(1ull<<24)|(1ull<<26)|(1ull<<34))

// 256-bit global load (Blackwell sm_100+), non-coherent path
static __device__ __forceinline__ void ldg256(const float4* p, float* v)
{
    asm("ld.global.nc.v8.f32 {%0,%1,%2,%3,%4,%5,%6,%7}, [%8];"
        : "=f"(v[0]), "=f"(v[1]), "=f"(v[2]), "=f"(v[3]),
          "=f"(v[4]), "=f"(v[5]), "=f"(v[6]), "=f"(v[7])
        : "l"(p));
}

// 256-bit global store
static __device__ __forceinline__ void stg256(float4* p, const float* v)
{
    asm volatile("st.global.v8.f32 [%0], {%1,%2,%3,%4,%5,%6,%7,%8};"
        :: "l"(p),
           "f"(v[0]), "f"(v[1]), "f"(v[2]), "f"(v[3]),
           "f"(v[4]), "f"(v[5]), "f"(v[6]), "f"(v[7])
        : "memory");
}

__global__ __launch_bounds__(TPB, 6) void xflat_rgb_extract_kernel(
    const float4* __restrict__ green,   // [B,1,H,W]
    const float4* __restrict__ xtrans,  // [B,3,H,W]
    const float4* __restrict__ chroma,  // [B,2,H,W]
    float4* __restrict__ out)           // [B,3,H,W]
{
    const int t = threadIdx.x;         // 0..191, one 32B chunk (8 floats)
    const int h = blockIdx.x;          // 0..1535
    const int b = blockIdx.y;          // 0..15

    // 6-bit row patterns tripled to 18 bits: bits c0..c0+7 valid for c0<=5
    const int r6 = h % 6;
    unsigned rrow = (unsigned)((R_MASK >> (r6 * 6)) & 63u);
    unsigned brow = (unsigned)((B_MASK >> (r6 * 6)) & 63u);
    rrow |= (rrow << 6);  rrow |= (rrow << 12) & 0x3F000u;
    brow |= (brow << 6);  brow |= (brow << 12) & 0x3F000u;

    const int c0 = (2 * t) % 6;        // (8t) mod 6

    const int rowOff = h * W4 + 2 * t; // float4 units, 32B aligned
    const int b1 = b * HW4;            // green plane base
    const int b2 = b * (2 * HW4);      // chroma base
    const int b3 = b * (3 * HW4);      // xtrans / out base

    float xv0[8], xv2[8], cv0[8], cv1[8], gv[8];
    ldg256(&xtrans[b3 + rowOff],           xv0);
    ldg256(&xtrans[b3 + 2 * HW4 + rowOff], xv2);
    ldg256(&chroma[b2 + rowOff],           cv0);
    ldg256(&chroma[b2 + HW4 + rowOff],     cv1);
    ldg256(&green [b1 + rowOff],           gv);

    float o0[8], o2[8];
#pragma unroll
    for (int i = 0; i < 8; i++) {
        o0[i] = ((rrow >> (c0 + i)) & 1u) ? xv0[i] : cv0[i];
        o2[i] = ((brow >> (c0 + i)) & 1u) ? xv2[i] : cv1[i];
    }

    stg256(&out[b3 + rowOff],           o0);
    stg256(&out[b3 + HW4 + rowOff],     gv);
    stg256(&out[b3 + 2 * HW4 + rowOff], o2);
}

extern "C" void kernel_launch(void* const* d_in, const int* in_sizes, int n_in,
                              void* d_out, int out_size)
{
    const float4* green  = (const float4*)d_in[0];  // green_pred  [16,1,1536,1536]
    const float4* xtrans = (const float4*)d_in[1];  // xtrans      [16,3,1536,1536]
    const float4* chroma = (const float4*)d_in[2];  // chroma_pred [16,2,1536,1536]
    float4* out = (float4*)d_out;                   // [16,3,1536,1536] float32

    dim3 grid(H_DIM, B_DIM);
    dim3 block(TPB);
    xflat_rgb_extract_kernel<<<grid, block>>>(green, xtrans, chroma, out);
}

// round 10
// speedup vs baseline: 1.0115x; 1.0115x over previous
#include <cuda_runtime.h>

// Problem constants (fixed shapes from reference: B=16, H=W=1536)
#define H_DIM  1536
#define W_DIM  1536
#define B_DIM  16
#define HW     (H_DIM * W_DIM)      // 2359296
#define HW4    (HW / 4)             // 589824 float4 per plane
#define W4     (W_DIM / 4)          // 384 float4 per row

// 36-bit tile masks, bit index = (r%6)*6 + (c%6)
// R_POS = (0,4)(1,0)(1,2)(2,4)(3,1)(4,3)(4,5)(5,1) -> bits 4,6,8,16,19,27,29,31
// B_POS = (0,1)(1,3)(1,5)(2,1)(3,4)(4,0)(4,2)(5,4) -> bits 1,9,11,13,22,24,26,34
#define R_MASK ((1ull<<4)|(1ull<<6)|(1ull<<8)|(1ull<<16)|(1ull<<19)|(1ull<<27)|(1ull<<29)|(1ull<<31))
#define B_MASK ((1ull<<1)|(1ull<<9)|(1ull<<11)|(1ull<<13)|(1ull<<22)|(1ull<<24)|(1ull<<26)|(1ull<<34))

__global__ __launch_bounds__(W4, 4) void xflat_rgb_extract_kernel(
    const float4* __restrict__ green,   // [B,1,H,W]
    const float4* __restrict__ xtrans,  // [B,3,H,W]
    const float4* __restrict__ chroma,  // [B,2,H,W]
    float4* __restrict__ out)           // [B,3,H,W]
{
    const int w4 = threadIdx.x;        // 0..383
    const int h  = blockIdx.x;         // 0..1535
    const int b  = blockIdx.y;         // 0..15

    // Row mask patterns: 6 bits, doubled to 12 so lanes c0..c0+3 index directly
    const int r6 = h % 6;
    unsigned rrow = (unsigned)((R_MASK >> (r6 * 6)) & 63u);
    unsigned brow = (unsigned)((B_MASK >> (r6 * 6)) & 63u);
    rrow |= rrow << 6;
    brow |= brow << 6;

    const int c0 = (w4 * 4) % 6;       // column residue of lane 0

    // float4-unit offsets
    const int rowOff = h * W4 + w4;
    const int b1 = b * HW4;            // green plane base
    const int b2 = b * (2 * HW4);      // chroma base
    const int b3 = b * (3 * HW4);      // xtrans / out base

    // 5 independent 128-bit loads (MLP=5)
    const float4 xv0 = xtrans[b3 + rowOff];
    const float4 xv2 = xtrans[b3 + 2 * HW4 + rowOff];
    const float4 cv0 = chroma[b2 + rowOff];
    const float4 cv1 = chroma[b2 + HW4 + rowOff];
    const float4 gv  = green [b1 + rowOff];

    float4 o0, o2;
    o0.x = ((rrow >> (c0 + 0)) & 1u) ? xv0.x : cv0.x;
    o0.y = ((rrow >> (c0 + 1)) & 1u) ? xv0.y : cv0.y;
    o0.z = ((rrow >> (c0 + 2)) & 1u) ? xv0.z : cv0.z;
    o0.w = ((rrow >> (c0 + 3)) & 1u) ? xv0.w : cv0.w;

    o2.x = ((brow >> (c0 + 0)) & 1u) ? xv2.x : cv1.x;
    o2.y = ((brow >> (c0 + 1)) & 1u) ? xv2.y : cv1.y;
    o2.z = ((brow >> (c0 + 2)) & 1u) ? xv2.z : cv1.z;
    o2.w = ((brow >> (c0 + 3)) & 1u) ? xv2.w : cv1.w;

    out[b3 + rowOff]           = o0;
    out[b3 + HW4 + rowOff]     = gv;
    out[b3 + 2 * HW4 + rowOff] = o2;
}

extern "C" void kernel_launch(void* const* d_in, const int* in_sizes, int n_in,
                              void* d_out, int out_size)
{
    const float4* green  = (const float4*)d_in[0];  // green_pred  [16,1,1536,1536]
    const float4* xtrans = (const float4*)d_in[1];  // xtrans      [16,3,1536,1536]
    const float4* chroma = (const float4*)d_in[2];  // chroma_pred [16,2,1536,1536]
    float4* out = (float4*)d_out;                   // [16,3,1536,1536] float32

    dim3 grid(H_DIM, B_DIM);
    dim3 block(W4);
    xflat_rgb_extract_kernel<<<grid, block>>>(green, xtrans, chroma, out);
}